// round 11
// baseline (speedup 1.0000x reference)
#include <cuda_runtime.h>
#include <cuda_bf16.h>
#include <cstdint>

#define NCTA_SM 7
#define NBLK (148 * NCTA_SM)
#define NTHR 128
#define WPB  (NTHR / 32)
#define NWARPS (NBLK * WPB)

// per-lane staging region: 8 chunks x 8B = 64B, padded to 80B (20 words) so the
// four LDS.128 readbacks are bank-conflict-free (lane*20 mod 32 hits distinct
// bank quads). Per warp buffer = 32*80 = 2560B, double-buffered.
#define LANE_STRIDE 80
#define BUF_BYTES   (32 * LANE_STRIDE)
#define STAGE_BYTES (WPB * 2 * BUF_BYTES)

static __device__ __forceinline__ float tanh_fast(float x) {
    float r; asm("tanh.approx.f32 %0, %1;" : "=f"(r) : "f"(x)); return r;
}
static __device__ __forceinline__ uint32_t bfpack(float lo, float hi) {
    __nv_bfloat162 v = __floats2bfloat162_rn(lo, hi);
    return *reinterpret_cast<uint32_t*>(&v);
}
static __device__ __forceinline__ float bfres(float x) {
    return x - __bfloat162float(__float2bfloat16_rn(x));
}
// high 16 bits of two f32 -> bf16x2 (truncation split)
static __device__ __forceinline__ uint32_t hi2(float a, float b) {
    uint32_t r;
    asm("prmt.b32 %0, %1, %2, 0x7632;" : "=r"(r)
        : "r"(__float_as_uint(a)), "r"(__float_as_uint(b)));
    return r;
}
static __device__ __forceinline__ float trunc_res(float x) {
    return x - __uint_as_float(__float_as_uint(x) & 0xFFFF0000u);
}
static __device__ __forceinline__ void mma_bf16(
    float& c0, float& c1, float& c2, float& c3,
    uint32_t a0, uint32_t a1, uint32_t a2, uint32_t a3,
    uint32_t b0, uint32_t b1)
{
    asm volatile(
        "mma.sync.aligned.m16n8k16.row.col.f32.bf16.bf16.f32 "
        "{%0,%1,%2,%3},{%4,%5,%6,%7},{%8,%9},{%0,%1,%2,%3};"
        : "+f"(c0), "+f"(c1), "+f"(c2), "+f"(c3)
        : "r"(a0), "r"(a1), "r"(a2), "r"(a3), "r"(b0), "r"(b1));
}
static __device__ __forceinline__ uint32_t cvta_smem(const void* p) {
    uint32_t a;
    asm("{ .reg .u64 t; cvta.to.shared.u64 t, %1; cvt.u32.u64 %0, t; }" : "=r"(a) : "l"(p));
    return a;
}
static __device__ __forceinline__ void cp8(uint32_t dst, const float* src) {
    asm volatile("cp.async.ca.shared.global [%0], [%1], 8;" :: "r"(dst), "l"(src));
}
static __device__ __forceinline__ void cp_commit() {
    asm volatile("cp.async.commit_group;" ::: "memory");
}
template <int N>
static __device__ __forceinline__ void cp_wait() {
    asm volatile("cp.async.wait_group %0;" :: "n"(N) : "memory");
}

// Stage one 32-node tile's per-lane fragments into smem via cp.async.
// Chunk k (0..7): row = tile*32 + g + (k>>1)*8, colpair = 2t + (k&1)*8.
static __device__ __forceinline__ void stage_tile(
    const float* __restrict__ x, int tile, int n,
    uint32_t dst_lane_base, int g, int t)
{
    const int rbase = tile * 32 + g;
#pragma unroll
    for (int k = 0; k < 8; k++) {
        const int row = rbase + (k >> 1) * 8;
        const float* src = x + (size_t)row * 16 + (2 * t + (k & 1) * 8);
        if (row < n) cp8(dst_lane_base + k * 8, src);
    }
    cp_commit();
}

// out[i] = relu((1 - sigmoid(x@Wz' + bz')) * tanh(x@Wh' + bh')) @ Wlin + blin
// (H=0 collapses the GRU; edge inputs mathematically unused for ChebConv K=1.)
// mma.sync bf16, 3-product hi/lo split; x staged gmem->smem via cp.async
// (double-buffered per warp) so no register-resident prefetch -> higher occ.
__global__ void __launch_bounds__(NTHR, NCTA_SM) gru_mma_kernel(
    const float* __restrict__ x,
    const float* __restrict__ Wxz, const float* __restrict__ bxz,
    const float* __restrict__ bhz,
    const float* __restrict__ Wxh, const float* __restrict__ bxh,
    const float* __restrict__ bhh,
    const float* __restrict__ Wlin, const float* __restrict__ blin,
    float* __restrict__ out, int n)
{
    __shared__ uint4  sB[8][32];     // (hi0, hi1, lo0, lo1) per lane per n-chunk
    __shared__ float4 sBias[4][32];  // (z0, z1, h0, h1) for chunk pair (j, j+4)
    __shared__ float2 sWl[4][32];    // (wl0, wl1) per chunk pair, 0.5 folded
    __shared__ float  sBl;
    extern __shared__ char xstage[];

    const int lane = threadIdx.x & 31;
    const int wid  = threadIdx.x >> 5;
    const int g    = lane >> 2;
    const int t    = lane & 3;

    // ---- warp 0: stage lane-indexed constants ------------------------------
    if (wid == 0) {
#pragma unroll
        for (int j = 0; j < 8; j++) {
            const bool zside = (j < 4);
            const float sc = zside ? 0.5f : 1.0f;
            const float* W = zside ? Wxz : Wxh;
            const int c = zside ? (8 * j + g) : (8 * (j - 4) + g);
            const float w0 = sc * __ldg(&W[(2 * t)     * 32 + c]);
            const float w1 = sc * __ldg(&W[(2 * t + 1) * 32 + c]);
            const float w2 = sc * __ldg(&W[(2 * t + 8) * 32 + c]);
            const float w3 = sc * __ldg(&W[(2 * t + 9) * 32 + c]);
            sB[j][lane] = make_uint4(bfpack(w0, w1), bfpack(w2, w3),
                                     bfpack(bfres(w0), bfres(w1)),
                                     bfpack(bfres(w2), bfres(w3)));
        }
#pragma unroll
        for (int j = 0; j < 4; j++) {
            const int zc = 8 * j + 2 * t;
            sBias[j][lane] = make_float4(
                0.5f * (__ldg(&bxz[zc])     + __ldg(&bhz[zc])),
                0.5f * (__ldg(&bxz[zc + 1]) + __ldg(&bhz[zc + 1])),
                __ldg(&bxh[zc])     + __ldg(&bhh[zc]),
                __ldg(&bxh[zc + 1]) + __ldg(&bhh[zc + 1]));
            sWl[j][lane] = make_float2(0.5f * __ldg(&Wlin[zc]),
                                       0.5f * __ldg(&Wlin[zc + 1]));
        }
        if (lane == 0) sBl = __ldg(&blin[0]);
    }
    __syncthreads();

    const int nt32 = (n + 31) >> 5;               // 32-node tiles
    int tile = blockIdx.x * WPB + wid;
    if (tile >= nt32) return;

    const float bl = sBl;
    const uint32_t warp_stage =
        cvta_smem(xstage) + (uint32_t)wid * 2 * BUF_BYTES + (uint32_t)lane * LANE_STRIDE;

    // prologue: stage tile 0 into phase 0
    stage_tile(x, tile, n, warp_stage, g, t);

    int phase = 0;
#pragma unroll 1
    while (true) {
        const int tnext = tile + NWARPS;
        const bool hasnext = (tnext < nt32);
        if (hasnext) {
            stage_tile(x, tnext, n, warp_stage + (phase ^ 1) * BUF_BYTES, g, t);
            cp_wait<1>();     // current tile's group done; next stays in flight
        } else {
            cp_wait<0>();
        }

        // readback current tile: 4 conflict-free LDS.128
        const char* rb = xstage + ((size_t)wid * 2 + phase) * BUF_BYTES
                       + (size_t)lane * LANE_STRIDE;
        const float4 v0 = *reinterpret_cast<const float4*>(rb);
        const float4 v1 = *reinterpret_cast<const float4*>(rb + 16);
        const float4 v2 = *reinterpret_cast<const float4*>(rb + 32);
        const float4 v3 = *reinterpret_cast<const float4*>(rb + 48);

        // A fragments: truncation hi + bf16 residual lo
        const uint32_t ahA0 = hi2(v0.x, v0.y), ahA2 = hi2(v0.z, v0.w);
        const uint32_t ahA1 = hi2(v1.x, v1.y), ahA3 = hi2(v1.z, v1.w);
        const uint32_t ahB0 = hi2(v2.x, v2.y), ahB2 = hi2(v2.z, v2.w);
        const uint32_t ahB1 = hi2(v3.x, v3.y), ahB3 = hi2(v3.z, v3.w);
        const uint32_t alA0 = bfpack(trunc_res(v0.x), trunc_res(v0.y));
        const uint32_t alA2 = bfpack(trunc_res(v0.z), trunc_res(v0.w));
        const uint32_t alA1 = bfpack(trunc_res(v1.x), trunc_res(v1.y));
        const uint32_t alA3 = bfpack(trunc_res(v1.z), trunc_res(v1.w));
        const uint32_t alB0 = bfpack(trunc_res(v2.x), trunc_res(v2.y));
        const uint32_t alB2 = bfpack(trunc_res(v2.z), trunc_res(v2.w));
        const uint32_t alB1 = bfpack(trunc_res(v3.x), trunc_res(v3.y));
        const uint32_t alB3 = bfpack(trunc_res(v3.z), trunc_res(v3.w));

        const int node0 = tile * 32 + g;

        float r0 = 0.0f, r1 = 0.0f, r2 = 0.0f, r3 = 0.0f;
#pragma unroll
        for (int jp = 0; jp < 4; jp++) {
            const uint4  bz = sB[jp][lane];        // Z-side W frags (hi, lo)
            const uint4  bh = sB[jp + 4][lane];    // H-side W frags
            const float4 bi = sBias[jp][lane];
            const float2 w  = sWl[jp][lane];

            float zA0 = bi.x, zA1 = bi.y, zA2 = bi.x, zA3 = bi.y;
            float hA0 = bi.z, hA1 = bi.w, hA2 = bi.z, hA3 = bi.w;
            float zB0 = bi.x, zB1 = bi.y, zB2 = bi.x, zB3 = bi.y;
            float hB0 = bi.z, hB1 = bi.w, hB2 = bi.z, hB3 = bi.w;

            mma_bf16(zA0, zA1, zA2, zA3, ahA0, ahA1, ahA2, ahA3, bz.x, bz.y);
            mma_bf16(zB0, zB1, zB2, zB3, ahB0, ahB1, ahB2, ahB3, bz.x, bz.y);
            mma_bf16(hA0, hA1, hA2, hA3, ahA0, ahA1, ahA2, ahA3, bh.x, bh.y);
            mma_bf16(hB0, hB1, hB2, hB3, ahB0, ahB1, ahB2, ahB3, bh.x, bh.y);
            mma_bf16(zA0, zA1, zA2, zA3, alA0, alA1, alA2, alA3, bz.x, bz.y);
            mma_bf16(zB0, zB1, zB2, zB3, alB0, alB1, alB2, alB3, bz.x, bz.y);
            mma_bf16(hA0, hA1, hA2, hA3, alA0, alA1, alA2, alA3, bh.x, bh.y);
            mma_bf16(hB0, hB1, hB2, hB3, alB0, alB1, alB2, alB3, bh.x, bh.y);
            mma_bf16(zA0, zA1, zA2, zA3, ahA0, ahA1, ahA2, ahA3, bz.z, bz.w);
            mma_bf16(zB0, zB1, zB2, zB3, ahB0, ahB1, ahB2, ahB3, bz.z, bz.w);
            mma_bf16(hA0, hA1, hA2, hA3, ahA0, ahA1, ahA2, ahA3, bh.z, bh.w);
            mma_bf16(hB0, hB1, hB2, hB3, ahB0, ahB1, ahB2, ahB3, bh.z, bh.w);

            // epilogue for this chunk pair: p = (1 - t1) * t2, 0.5 in wlin
            float t1, t2, pp;
            t1 = tanh_fast(zA0); t2 = tanh_fast(hA0);
            pp = t2 - t1 * t2; r0 = fmaf(fmaxf(pp, 0.0f), w.x, r0);
            t1 = tanh_fast(zA1); t2 = tanh_fast(hA1);
            pp = t2 - t1 * t2; r0 = fmaf(fmaxf(pp, 0.0f), w.y, r0);
            t1 = tanh_fast(zA2); t2 = tanh_fast(hA2);
            pp = t2 - t1 * t2; r1 = fmaf(fmaxf(pp, 0.0f), w.x, r1);
            t1 = tanh_fast(zA3); t2 = tanh_fast(hA3);
            pp = t2 - t1 * t2; r1 = fmaf(fmaxf(pp, 0.0f), w.y, r1);
            t1 = tanh_fast(zB0); t2 = tanh_fast(hB0);
            pp = t2 - t1 * t2; r2 = fmaf(fmaxf(pp, 0.0f), w.x, r2);
            t1 = tanh_fast(zB1); t2 = tanh_fast(hB1);
            pp = t2 - t1 * t2; r2 = fmaf(fmaxf(pp, 0.0f), w.y, r2);
            t1 = tanh_fast(zB2); t2 = tanh_fast(hB2);
            pp = t2 - t1 * t2; r3 = fmaf(fmaxf(pp, 0.0f), w.x, r3);
            t1 = tanh_fast(zB3); t2 = tanh_fast(hB3);
            pp = t2 - t1 * t2; r3 = fmaf(fmaxf(pp, 0.0f), w.y, r3);
        }

        r0 += __shfl_xor_sync(0xFFFFFFFFu, r0, 1);
        r0 += __shfl_xor_sync(0xFFFFFFFFu, r0, 2);
        r1 += __shfl_xor_sync(0xFFFFFFFFu, r1, 1);
        r1 += __shfl_xor_sync(0xFFFFFFFFu, r1, 2);
        r2 += __shfl_xor_sync(0xFFFFFFFFu, r2, 1);
        r2 += __shfl_xor_sync(0xFFFFFFFFu, r2, 2);
        r3 += __shfl_xor_sync(0xFFFFFFFFu, r3, 1);
        r3 += __shfl_xor_sync(0xFFFFFFFFu, r3, 2);
        if (t == 0) {
            if (node0 < n)      out[node0]      = r0 + bl;
            if (node0 + 8 < n)  out[node0 + 8]  = r1 + bl;
            if (node0 + 16 < n) out[node0 + 16] = r2 + bl;
            if (node0 + 24 < n) out[node0 + 24] = r3 + bl;
        }

        if (!hasnext) break;
        tile = tnext;
        phase ^= 1;
    }
}

extern "C" void kernel_launch(void* const* d_in, const int* in_sizes, int n_in,
                              void* d_out, int out_size)
{
    // 0=x, 1=edge_index(unused), 2=edge_weight(unused), 3=Wxz, 4=bxz, 5=Whz(u), 6=bhz,
    // 7=Wxr(u), 8=bxr(u), 9=Whr(u), 10=bhr(u), 11=Wxh, 12=bxh, 13=Whh(u), 14=bhh,
    // 15=Wlin, 16=blin
    const float* x    = (const float*)d_in[0];
    const float* Wxz  = (const float*)d_in[3];
    const float* bxz  = (const float*)d_in[4];
    const float* bhz  = (const float*)d_in[6];
    const float* Wxh  = (const float*)d_in[11];
    const float* bxh  = (const float*)d_in[12];
    const float* bhh  = (const float*)d_in[14];
    const float* Wlin = (const float*)d_in[15];
    const float* blin = (const float*)d_in[16];

    const int n = in_sizes[0] / 16;
    gru_mma_kernel<<<NBLK, NTHR, STAGE_BYTES>>>(x, Wxz, bxz, bhz, Wxh, bxh, bhh,
                                                Wlin, blin, (float*)d_out, n);
}

// round 12
// speedup vs baseline: 1.1750x; 1.1750x over previous
#include <cuda_runtime.h>
#include <cuda_bf16.h>
#include <cstdint>

#define NCTA_SM 6
#define NBLK (148 * NCTA_SM)
#define NTHR 128
#define WPB  (NTHR / 32)
#define NWARPS (NBLK * WPB)

static __device__ __forceinline__ float tanh_fast(float x) {
    float r; asm("tanh.approx.f32 %0, %1;" : "=f"(r) : "f"(x)); return r;
}
static __device__ __forceinline__ uint32_t tf32r(float x) {   // round f32 -> tf32 (RNA)
    uint32_t r; asm("cvt.rna.tf32.f32 %0, %1;" : "=r"(r) : "f"(x)); return r;
}
static __device__ __forceinline__ void mma_tf32(
    float& c0, float& c1, float& c2, float& c3,
    uint32_t a0, uint32_t a1, uint32_t a2, uint32_t a3,
    uint32_t b0, uint32_t b1)
{
    asm volatile(
        "mma.sync.aligned.m16n8k8.row.col.f32.tf32.tf32.f32 "
        "{%0,%1,%2,%3},{%4,%5,%6,%7},{%8,%9},{%0,%1,%2,%3};"
        : "+f"(c0), "+f"(c1), "+f"(c2), "+f"(c3)
        : "r"(a0), "r"(a1), "r"(a2), "r"(a3), "r"(b0), "r"(b1));
}
static __device__ __forceinline__ float2 ldx2g(const float* __restrict__ x, int row, int col, int n) {
    if (row < n) return *reinterpret_cast<const float2*>(x + (size_t)row * 16 + col);
    return make_float2(0.0f, 0.0f);
}

// out[i] = relu((1 - sigmoid(x@Wz' + bz')) * tanh(x@Wh' + bh')) @ Wlin + blin
// (H=0 collapses the GRU; edge inputs mathematically unused for ChebConv K=1.)
// TF32 single-product mma.m16n8k8. K-order permuted (feature 2t -> k=t,
// 2t+1 -> k=t+4, 2t+8 -> k=t+8, 2t+9 -> k=t+12) so A fragments are exactly the
// float2 pairs each lane loads and B fragments the 4 weights it stages.
// Z-side pre-scaled by 0.5: 1-sigmoid(a) = 0.5*(1 - tanh(a')), 0.5 in Wlin.
__global__ void __launch_bounds__(NTHR, NCTA_SM) gru_mma_kernel(
    const float* __restrict__ x,
    const float* __restrict__ Wxz, const float* __restrict__ bxz,
    const float* __restrict__ bhz,
    const float* __restrict__ Wxh, const float* __restrict__ bxh,
    const float* __restrict__ bhh,
    const float* __restrict__ Wlin, const float* __restrict__ blin,
    float* __restrict__ out, int n)
{
    __shared__ uint4  sB[8][32];     // tf32 (W[2t], W[2t+1], W[2t+8], W[2t+9]) col g
    __shared__ float4 sBias[4][32];  // (z0, z1, h0, h1) for chunk pair (j, j+4)
    __shared__ float2 sWl[4][32];    // (wl0, wl1) per chunk pair, 0.5 folded
    __shared__ float  sBl;

    const int lane = threadIdx.x & 31;
    const int wid  = threadIdx.x >> 5;
    const int g    = lane >> 2;
    const int t    = lane & 3;

    // ---- warp 0: stage lane-indexed constants ------------------------------
    if (wid == 0) {
#pragma unroll
        for (int j = 0; j < 8; j++) {
            const bool zside = (j < 4);
            const float sc = zside ? 0.5f : 1.0f;
            const float* W = zside ? Wxz : Wxh;
            const int c = zside ? (8 * j + g) : (8 * (j - 4) + g);
            const float w0 = sc * __ldg(&W[(2 * t)     * 32 + c]);
            const float w1 = sc * __ldg(&W[(2 * t + 1) * 32 + c]);
            const float w2 = sc * __ldg(&W[(2 * t + 8) * 32 + c]);
            const float w3 = sc * __ldg(&W[(2 * t + 9) * 32 + c]);
            sB[j][lane] = make_uint4(tf32r(w0), tf32r(w1), tf32r(w2), tf32r(w3));
        }
#pragma unroll
        for (int j = 0; j < 4; j++) {
            const int zc = 8 * j + 2 * t;
            sBias[j][lane] = make_float4(
                0.5f * (__ldg(&bxz[zc])     + __ldg(&bhz[zc])),
                0.5f * (__ldg(&bxz[zc + 1]) + __ldg(&bhz[zc + 1])),
                __ldg(&bxh[zc])     + __ldg(&bhh[zc]),
                __ldg(&bxh[zc + 1]) + __ldg(&bhh[zc + 1]));
            sWl[j][lane] = make_float2(0.5f * __ldg(&Wlin[zc]),
                                       0.5f * __ldg(&Wlin[zc + 1]));
        }
        if (lane == 0) sBl = __ldg(&blin[0]);
    }
    __syncthreads();

    const int nt32 = (n + 31) >> 5;               // 32-node tiles
    int tile = blockIdx.x * WPB + wid;
    if (tile >= nt32) return;

    const float bl = sBl;
    const long long step = (long long)NWARPS * 512;
    const float* p = x + (size_t)tile * 512 + (size_t)(g * 16 + 2 * t);

    // x values: set A rows {g, g+8}, set B rows {16+g, 24+g}; cols {2t,2t+1} & {2t+8,2t+9}
    float2 c00, c01, c10, c11, d00, d01, d10, d11;
    if (tile * 32 + 32 <= n) {
        c00 = *(const float2*)(p);        c01 = *(const float2*)(p + 8);
        c10 = *(const float2*)(p + 128);  c11 = *(const float2*)(p + 136);
        d00 = *(const float2*)(p + 256);  d01 = *(const float2*)(p + 264);
        d10 = *(const float2*)(p + 384);  d11 = *(const float2*)(p + 392);
    } else {
        const int b = tile * 32;
        c00 = ldx2g(x, b + g,      2 * t,     n);
        c01 = ldx2g(x, b + g,      2 * t + 8, n);
        c10 = ldx2g(x, b + g + 8,  2 * t,     n);
        c11 = ldx2g(x, b + g + 8,  2 * t + 8, n);
        d00 = ldx2g(x, b + g + 16, 2 * t,     n);
        d01 = ldx2g(x, b + g + 16, 2 * t + 8, n);
        d10 = ldx2g(x, b + g + 24, 2 * t,     n);
        d11 = ldx2g(x, b + g + 24, 2 * t + 8, n);
    }

#pragma unroll 1
    while (true) {
        // A fragments (tf32): chunk0 = {c00.x, c10.x, c00.y, c10.y} (k = t, t+4),
        //                     chunk1 = {c01.x, c11.x, c01.y, c11.y} (k = t+8, t+12)
        const uint32_t aA00 = tf32r(c00.x), aA01 = tf32r(c10.x);
        const uint32_t aA02 = tf32r(c00.y), aA03 = tf32r(c10.y);
        const uint32_t aA10 = tf32r(c01.x), aA11 = tf32r(c11.x);
        const uint32_t aA12 = tf32r(c01.y), aA13 = tf32r(c11.y);
        const uint32_t aB00 = tf32r(d00.x), aB01 = tf32r(d10.x);
        const uint32_t aB02 = tf32r(d00.y), aB03 = tf32r(d10.y);
        const uint32_t aB10 = tf32r(d01.x), aB11 = tf32r(d11.x);
        const uint32_t aB12 = tf32r(d01.y), aB13 = tf32r(d11.y);

        const int node0 = tile * 32 + g;
        const int tnext = tile + NWARPS;
        const bool hasnext = (tnext < nt32);
        if (hasnext) {                      // prefetch next tile under MMA+epilogue
            p += step;
            if (tnext * 32 + 32 <= n) {
                c00 = *(const float2*)(p);        c01 = *(const float2*)(p + 8);
                c10 = *(const float2*)(p + 128);  c11 = *(const float2*)(p + 136);
                d00 = *(const float2*)(p + 256);  d01 = *(const float2*)(p + 264);
                d10 = *(const float2*)(p + 384);  d11 = *(const float2*)(p + 392);
            } else {
                const int b = tnext * 32;
                c00 = ldx2g(x, b + g,      2 * t,     n);
                c01 = ldx2g(x, b + g,      2 * t + 8, n);
                c10 = ldx2g(x, b + g + 8,  2 * t,     n);
                c11 = ldx2g(x, b + g + 8,  2 * t + 8, n);
                d00 = ldx2g(x, b + g + 16, 2 * t,     n);
                d01 = ldx2g(x, b + g + 16, 2 * t + 8, n);
                d10 = ldx2g(x, b + g + 24, 2 * t,     n);
                d11 = ldx2g(x, b + g + 24, 2 * t + 8, n);
            }
        }

        float r0 = 0.0f, r1 = 0.0f, r2 = 0.0f, r3 = 0.0f;
#pragma unroll
        for (int jp = 0; jp < 4; jp++) {
            const uint4  bz = sB[jp][lane];        // Z-side W frags (chunk0: x,y; chunk1: z,w)
            const uint4  bh = sB[jp + 4][lane];    // H-side W frags
            const float4 bi = sBias[jp][lane];
            const float2 w  = sWl[jp][lane];

            float zA0 = bi.x, zA1 = bi.y, zA2 = bi.x, zA3 = bi.y;
            float hA0 = bi.z, hA1 = bi.w, hA2 = bi.z, hA3 = bi.w;
            float zB0 = bi.x, zB1 = bi.y, zB2 = bi.x, zB3 = bi.y;
            float hB0 = bi.z, hB1 = bi.w, hB2 = bi.z, hB3 = bi.w;

            mma_tf32(zA0, zA1, zA2, zA3, aA00, aA01, aA02, aA03, bz.x, bz.y);
            mma_tf32(zB0, zB1, zB2, zB3, aB00, aB01, aB02, aB03, bz.x, bz.y);
            mma_tf32(hA0, hA1, hA2, hA3, aA00, aA01, aA02, aA03, bh.x, bh.y);
            mma_tf32(hB0, hB1, hB2, hB3, aB00, aB01, aB02, aB03, bh.x, bh.y);
            mma_tf32(zA0, zA1, zA2, zA3, aA10, aA11, aA12, aA13, bz.z, bz.w);
            mma_tf32(zB0, zB1, zB2, zB3, aB10, aB11, aB12, aB13, bz.z, bz.w);
            mma_tf32(hA0, hA1, hA2, hA3, aA10, aA11, aA12, aA13, bh.z, bh.w);
            mma_tf32(hB0, hB1, hB2, hB3, aB10, aB11, aB12, aB13, bh.z, bh.w);

            // epilogue for this chunk pair: p = (1 - t1) * t2, 0.5 in wlin
            float t1, t2, pp;
            t1 = tanh_fast(zA0); t2 = tanh_fast(hA0);
            pp = t2 - t1 * t2; r0 = fmaf(fmaxf(pp, 0.0f), w.x, r0);
            t1 = tanh_fast(zA1); t2 = tanh_fast(hA1);
            pp = t2 - t1 * t2; r0 = fmaf(fmaxf(pp, 0.0f), w.y, r0);
            t1 = tanh_fast(zA2); t2 = tanh_fast(hA2);
            pp = t2 - t1 * t2; r1 = fmaf(fmaxf(pp, 0.0f), w.x, r1);
            t1 = tanh_fast(zA3); t2 = tanh_fast(hA3);
            pp = t2 - t1 * t2; r1 = fmaf(fmaxf(pp, 0.0f), w.y, r1);
            t1 = tanh_fast(zB0); t2 = tanh_fast(hB0);
            pp = t2 - t1 * t2; r2 = fmaf(fmaxf(pp, 0.0f), w.x, r2);
            t1 = tanh_fast(zB1); t2 = tanh_fast(hB1);
            pp = t2 - t1 * t2; r2 = fmaf(fmaxf(pp, 0.0f), w.y, r2);
            t1 = tanh_fast(zB2); t2 = tanh_fast(hB2);
            pp = t2 - t1 * t2; r3 = fmaf(fmaxf(pp, 0.0f), w.x, r3);
            t1 = tanh_fast(zB3); t2 = tanh_fast(hB3);
            pp = t2 - t1 * t2; r3 = fmaf(fmaxf(pp, 0.0f), w.y, r3);
        }

        r0 += __shfl_xor_sync(0xFFFFFFFFu, r0, 1);
        r0 += __shfl_xor_sync(0xFFFFFFFFu, r0, 2);
        r1 += __shfl_xor_sync(0xFFFFFFFFu, r1, 1);
        r1 += __shfl_xor_sync(0xFFFFFFFFu, r1, 2);
        r2 += __shfl_xor_sync(0xFFFFFFFFu, r2, 1);
        r2 += __shfl_xor_sync(0xFFFFFFFFu, r2, 2);
        r3 += __shfl_xor_sync(0xFFFFFFFFu, r3, 1);
        r3 += __shfl_xor_sync(0xFFFFFFFFu, r3, 2);
        if (t == 0) {
            if (node0 < n)      out[node0]      = r0 + bl;
            if (node0 + 8 < n)  out[node0 + 8]  = r1 + bl;
            if (node0 + 16 < n) out[node0 + 16] = r2 + bl;
            if (node0 + 24 < n) out[node0 + 24] = r3 + bl;
        }

        if (!hasnext) break;
        tile = tnext;
    }
}

extern "C" void kernel_launch(void* const* d_in, const int* in_sizes, int n_in,
                              void* d_out, int out_size)
{
    // 0=x, 1=edge_index(unused), 2=edge_weight(unused), 3=Wxz, 4=bxz, 5=Whz(u), 6=bhz,
    // 7=Wxr(u), 8=bxr(u), 9=Whr(u), 10=bhr(u), 11=Wxh, 12=bxh, 13=Whh(u), 14=bhh,
    // 15=Wlin, 16=blin
    const float* x    = (const float*)d_in[0];
    const float* Wxz  = (const float*)d_in[3];
    const float* bxz  = (const float*)d_in[4];
    const float* bhz  = (const float*)d_in[6];
    const float* Wxh  = (const float*)d_in[11];
    const float* bxh  = (const float*)d_in[12];
    const float* bhh  = (const float*)d_in[14];
    const float* Wlin = (const float*)d_in[15];
    const float* blin = (const float*)d_in[16];

    const int n = in_sizes[0] / 16;
    gru_mma_kernel<<<NBLK, NTHR>>>(x, Wxz, bxz, bhz, Wxh, bxh, bhh,
                                   Wlin, blin, (float*)d_out, n);
}